// round 12
// baseline (speedup 1.0000x reference)
#include <cuda_runtime.h>
#include <math_constants.h>
#include <cstdint>

#define B_ 4
#define S_ 512
#define D_ 768
#define MAX_LEN_ 10
#define LEN_EMB_ 25
#define NUM_LABELS_ 9
#define N_ (S_ * MAX_LEN_)   // 5120
#define RED_STRIDE 100       // 96 partials + pad

// len_logits[L-1][c] = len_emb_table[L-1] . W[768:, c] + b[c]
__device__ float g_len_logits[MAX_LEN_ * NUM_LABELS_];
// Transposed W head: Wt[c][d] = W[d][c]
__device__ __align__(16) float g_Wt[NUM_LABELS_][D_];

__global__ void prep_kernel(const float* __restrict__ len_emb_table,
                            const float* __restrict__ W,
                            const float* __restrict__ bvec) {
    int i = blockIdx.x * 256 + threadIdx.x;
    if (i < NUM_LABELS_ * D_) {
        int c = i / D_;
        int d = i % D_;
        g_Wt[c][d] = W[(size_t)d * NUM_LABELS_ + c];
    }
    if (blockIdx.x == 0 && threadIdx.x < MAX_LEN_ * NUM_LABELS_) {
        int L = threadIdx.x / NUM_LABELS_;
        int c = threadIdx.x % NUM_LABELS_;
        float s = bvec[c];
        #pragma unroll
        for (int k = 0; k < LEN_EMB_; k++) {
            s = fmaf(len_emb_table[L * LEN_EMB_ + k], W[(D_ + k) * NUM_LABELS_ + c], s);
        }
        g_len_logits[threadIdx.x] = s;
    }
}

__device__ __forceinline__ float4 max4(float4 a, float4 b) {
    float4 r;
    r.x = fmaxf(a.x, b.x); r.y = fmaxf(a.y, b.y);
    r.z = fmaxf(a.z, b.z); r.w = fmaxf(a.w, b.w);
    return r;
}

__device__ __forceinline__ unsigned long long pack2(float lo, float hi) {
    unsigned long long r;
    asm("mov.b64 %0, {%1, %2};" : "=l"(r) : "f"(lo), "f"(hi));
    return r;
}
__device__ __forceinline__ unsigned long long mul2(unsigned long long a,
                                                   unsigned long long b) {
    unsigned long long r;
    asm("mul.rn.f32x2 %0, %1, %2;" : "=l"(r) : "l"(a), "l"(b));
    return r;
}
__device__ __forceinline__ void fma2(unsigned long long& d,
                                     unsigned long long a, unsigned long long b) {
    asm("fma.rn.f32x2 %0, %1, %2, %0;" : "+l"(d) : "l"(a), "l"(b));
}
__device__ __forceinline__ float hsum2(unsigned long long v) {
    float lo, hi;
    asm("mov.b64 {%0, %1}, %2;" : "=f"(lo), "=f"(hi) : "l"(v));
    return lo + hi;
}
// W re-load per row: volatile so ptxas cannot hoist these into long-lived
// registers (that's exactly the 72-reg pressure we're removing). v2.b64 gives
// two fma2-ready packed operands directly.
__device__ __forceinline__ void ldw2(const float* p,
                                     unsigned long long& a, unsigned long long& b) {
    asm volatile("ld.global.ca.v2.b64 {%0, %1}, [%2];"
                 : "=l"(a), "=l"(b) : "l"(p));
}

// One 96-thread block per (batch, start). Pure D-split: warp w owns dims
// [256w, 256w+256) (8 dims/lane), all 9 columns. Rows read once per block.
// Per row: prefix-max update, re-load the lane's W slice from global
// (L1-resident, volatile, no reg pressure), 9x (mul2+3 fma2) dot partials,
// 9 conflict-free STS.32 snapshots. TWO passes of 5 rows each against an
// 18KB red buffer (occupancy!), each followed by a conflict-free 96-wide
// transpose-reduce. Zero shuffles.
__global__ __launch_bounds__(96, 9) void span_ner_kernel(
    const float* __restrict__ we,       // [B, S, D]
    const int*   __restrict__ starts,   // [B, N]
    const int*   __restrict__ lens,     // [B, N]
    float*       __restrict__ out)      // [B, N, 9]
{
    __shared__ float red[5 * NUM_LABELS_][RED_STRIDE];  // 18 KB

    const int lane = threadIdx.x & 31;
    const int wid  = threadIdx.x >> 5;

    // Lane's dims: d0 = 256*wid + 4*lane (float4), and d0 + 128 (float4).
    const int d0 = 256 * wid + 4 * lane;

    const int bs = blockIdx.x;
    const int b = bs >> 9;               // /512
    const int s = bs & (S_ - 1);

    const size_t bn = (size_t)b * N_ + (size_t)s * MAX_LEN_;
    const int start = starts[bn];
    const int smax1 = S_ - start - 1;    // >= 0
    const float* base = we + ((size_t)b * S_ + start) * D_ + d0;

    float4 m0 = make_float4(-CUDART_INF_F, -CUDART_INF_F, -CUDART_INF_F, -CUDART_INF_F);
    float4 m1 = m0;

    const int t96 = 32 * wid + lane;     // partial column index 0..95

    #pragma unroll
    for (int pass = 0; pass < 2; pass++) {
        // ---- snapshot pass: rows 5*pass .. 5*pass+4
        #pragma unroll
        for (int rr = 0; rr < 5; rr++) {
            const int r = pass * 5 + rr;
            const int rc = (r < smax1) ? r : smax1;    // clamped (idempotent)
            const float* rowp = base + (size_t)rc * D_;
            float4 v0 = __ldg((const float4*)rowp);
            float4 v1 = __ldg((const float4*)(rowp + 128));
            m0 = max4(m0, v0);
            m1 = max4(m1, v1);

            const unsigned long long p0 = pack2(m0.x, m0.y);
            const unsigned long long p1 = pack2(m0.z, m0.w);
            const unsigned long long p2 = pack2(m1.x, m1.y);
            const unsigned long long p3 = pack2(m1.z, m1.w);

            #pragma unroll
            for (int c = 0; c < NUM_LABELS_; c++) {
                unsigned long long wa0, wa1, wb0, wb1;
                ldw2(&g_Wt[c][d0], wa0, wa1);
                ldw2(&g_Wt[c][d0 + 128], wb0, wb1);
                unsigned long long a = mul2(p0, wa0);
                fma2(a, p1, wa1);
                fma2(a, p2, wb0);
                fma2(a, p3, wb1);
                red[rr * NUM_LABELS_ + c][t96] = hsum2(a);   // conflict-free STS.32
            }
        }
        __syncthreads();

        // ---- reduce pass: 45 outputs (j = 5*pass .. 5*pass+4, c = 0..8).
        // Lane handles ol = wid*15 + lane (lane < 15); row starts 4*ol mod 32
        // distinct within each 8-lane LDS phase -> conflict-free LDS.128.
        if (lane < 15) {
            const int ol = wid * 15 + lane;              // 0..44
            const float4* rp = (const float4*)red[ol];
            float4 t0 = rp[0], t1 = rp[1], t2 = rp[2], t3 = rp[3];
            float4 t4 = rp[4], t5 = rp[5], t6 = rp[6], t7 = rp[7];
            #pragma unroll
            for (int g = 8; g < 24; g += 8) {
                float4 u0 = rp[g], u1 = rp[g+1], u2 = rp[g+2], u3 = rp[g+3];
                float4 u4 = rp[g+4], u5 = rp[g+5], u6 = rp[g+6], u7 = rp[g+7];
                t0 = make_float4(t0.x + u0.x, t0.y + u0.y, t0.z + u0.z, t0.w + u0.w);
                t1 = make_float4(t1.x + u1.x, t1.y + u1.y, t1.z + u1.z, t1.w + u1.w);
                t2 = make_float4(t2.x + u2.x, t2.y + u2.y, t2.z + u2.z, t2.w + u2.w);
                t3 = make_float4(t3.x + u3.x, t3.y + u3.y, t3.z + u3.z, t3.w + u3.w);
                t4 = make_float4(t4.x + u4.x, t4.y + u4.y, t4.z + u4.z, t4.w + u4.w);
                t5 = make_float4(t5.x + u5.x, t5.y + u5.y, t5.z + u5.z, t5.w + u5.w);
                t6 = make_float4(t6.x + u6.x, t6.y + u6.y, t6.z + u6.z, t6.w + u6.w);
                t7 = make_float4(t7.x + u7.x, t7.y + u7.y, t7.z + u7.z, t7.w + u7.w);
            }
            t0 = make_float4(t0.x + t4.x, t0.y + t4.y, t0.z + t4.z, t0.w + t4.w);
            t1 = make_float4(t1.x + t5.x, t1.y + t5.y, t1.z + t5.z, t1.w + t5.w);
            t2 = make_float4(t2.x + t6.x, t2.y + t6.y, t2.z + t6.z, t2.w + t6.w);
            t3 = make_float4(t3.x + t7.x, t3.y + t7.y, t3.z + t7.z, t3.w + t7.w);
            t0 = make_float4(t0.x + t2.x, t0.y + t2.y, t0.z + t2.z, t0.w + t2.w);
            t1 = make_float4(t1.x + t3.x, t1.y + t3.y, t1.z + t3.z, t1.w + t3.w);
            const float tot = (t0.x + t1.x) + (t0.y + t1.y) + (t0.z + t1.z) + (t0.w + t1.w);

            const int j = pass * 5 + ol / NUM_LABELS_;
            const int c = ol - NUM_LABELS_ * (ol / NUM_LABELS_);
            const int L = __ldg(lens + bn + j);
            out[(bn + j) * NUM_LABELS_ + c] = tot + g_len_logits[(L - 1) * NUM_LABELS_ + c];
        }
        __syncthreads();   // protect red before next pass overwrites it
    }
}

extern "C" void kernel_launch(void* const* d_in, const int* in_sizes, int n_in,
                              void* d_out, int out_size) {
    const float* we     = (const float*)d_in[0];   // word_embeddings [B,S,D]
    const int*   starts = (const int*)d_in[1];     // span_starts [B,N]
    const int*   lens   = (const int*)d_in[2];     // span_lens [B,N]
    const float* let    = (const float*)d_in[3];   // len_emb_table [MAX_LEN, LEN_EMB]
    const float* W      = (const float*)d_in[4];   // W [D+LEN_EMB, 9]
    const float* bvec   = (const float*)d_in[5];   // b [9]
    float* out = (float*)d_out;

    prep_kernel<<<(NUM_LABELS_ * D_ + 255) / 256, 256>>>(let, W, bvec);

    span_ner_kernel<<<B_ * S_, 96>>>(we, starts, lens, out);
}

// round 13
// speedup vs baseline: 3.2048x; 3.2048x over previous
#include <cuda_runtime.h>
#include <math_constants.h>
#include <cstdint>

#define B_ 4
#define S_ 512
#define D_ 768
#define MAX_LEN_ 10
#define LEN_EMB_ 25
#define NUM_LABELS_ 9
#define N_ (S_ * MAX_LEN_)   // 5120
#define RED_STRIDE 196       // 192 partials + 4 pad; 49 granules (odd) per row

// len_logits[L-1][c] = len_emb_table[L-1] . W[768:, c] + b[c]
__device__ float g_len_logits[MAX_LEN_ * NUM_LABELS_];
// Transposed W head: Wt[c][d] = W[d][c]
__device__ __align__(16) float g_Wt[NUM_LABELS_][D_];

__global__ void prep_kernel(const float* __restrict__ len_emb_table,
                            const float* __restrict__ W,
                            const float* __restrict__ bvec) {
    int i = blockIdx.x * 256 + threadIdx.x;
    if (i < NUM_LABELS_ * D_) {
        int c = i / D_;
        int d = i % D_;
        g_Wt[c][d] = W[(size_t)d * NUM_LABELS_ + c];
    }
    if (blockIdx.x == 0 && threadIdx.x < MAX_LEN_ * NUM_LABELS_) {
        int L = threadIdx.x / NUM_LABELS_;
        int c = threadIdx.x % NUM_LABELS_;
        float s = bvec[c];
        #pragma unroll
        for (int k = 0; k < LEN_EMB_; k++) {
            s = fmaf(len_emb_table[L * LEN_EMB_ + k], W[(D_ + k) * NUM_LABELS_ + c], s);
        }
        g_len_logits[threadIdx.x] = s;
    }
}

__device__ __forceinline__ float4 max4(float4 a, float4 b) {
    float4 r;
    r.x = fmaxf(a.x, b.x); r.y = fmaxf(a.y, b.y);
    r.z = fmaxf(a.z, b.z); r.w = fmaxf(a.w, b.w);
    return r;
}

__device__ __forceinline__ unsigned long long pack2(float lo, float hi) {
    unsigned long long r;
    asm("mov.b64 %0, {%1, %2};" : "=l"(r) : "f"(lo), "f"(hi));
    return r;
}
__device__ __forceinline__ unsigned long long mul2(unsigned long long a,
                                                   unsigned long long b) {
    unsigned long long r;
    asm("mul.rn.f32x2 %0, %1, %2;" : "=l"(r) : "l"(a), "l"(b));
    return r;
}
__device__ __forceinline__ void fma2(unsigned long long& d,
                                     unsigned long long a, unsigned long long b) {
    asm("fma.rn.f32x2 %0, %1, %2, %0;" : "+l"(d) : "l"(a), "l"(b));
}
__device__ __forceinline__ float hsum2(unsigned long long v) {
    float lo, hi;
    asm("mov.b64 {%0, %1}, %2;" : "=f"(lo), "=f"(hi) : "l"(v));
    return lo + hi;    // reg-pair aliasing: unpack is free, 1 FADD
}

// One 192-thread block per (batch, start). Thread t owns dims [4t, 4t+4)
// (one float4; warp covers 128 contiguous dims -> perfectly coalesced rows,
// each row read ONCE per block). W slice is only 9 packed u64 pairs = 36 regs
// -> ~60 regs total, 5 blocks/SM. Per row: prefix-max update, 9x (mul2+fma2)
// dot partials (2-deep chain), 9 conflict-free STS.32 snapshots. Two passes
// of 5 rows against a 35.25KB red buffer; each pass ends with a conflict-free
// 192-wide transpose-reduce on 2 warps. Zero shuffles.
__global__ __launch_bounds__(192, 5) void span_ner_kernel(
    const float* __restrict__ we,       // [B, S, D]
    const int*   __restrict__ starts,   // [B, N]
    float*       __restrict__ out)      // [B, N, 9]
{
    __shared__ float red[5 * NUM_LABELS_][RED_STRIDE];  // 35.25 KB

    const int tid  = threadIdx.x;
    const int lane = tid & 31;
    const int wid  = tid >> 5;

    const int d0 = 4 * tid;              // this thread's 4 dims

    // W slice packed f32x2: 9 cols x 2 u64 = 18 u64 (36 regs), coalesced load.
    unsigned long long Wp[NUM_LABELS_][2];
    #pragma unroll
    for (int c = 0; c < NUM_LABELS_; c++) {
        float4 w = *(const float4*)&g_Wt[c][d0];
        Wp[c][0] = pack2(w.x, w.y);
        Wp[c][1] = pack2(w.z, w.w);
    }

    const int bs = blockIdx.x;
    const int b = bs >> 9;               // /512
    const int s = bs & (S_ - 1);

    const size_t bn = (size_t)b * N_ + (size_t)s * MAX_LEN_;
    const int start = starts[bn];
    const int smax1 = S_ - start - 1;    // >= 0
    const float* base = we + ((size_t)b * S_ + start) * D_ + d0;

    float4 m = make_float4(-CUDART_INF_F, -CUDART_INF_F, -CUDART_INF_F, -CUDART_INF_F);

    #pragma unroll
    for (int pass = 0; pass < 2; pass++) {
        // ---- snapshot pass: rows 5*pass .. 5*pass+4
        #pragma unroll
        for (int rr = 0; rr < 5; rr++) {
            const int r = pass * 5 + rr;
            const int rc = (r < smax1) ? r : smax1;    // clamp (idempotent: max)
            float4 v = __ldg((const float4*)(base + (size_t)rc * D_));
            m = max4(m, v);

            const unsigned long long p0 = pack2(m.x, m.y);
            const unsigned long long p1 = pack2(m.z, m.w);

            #pragma unroll
            for (int c = 0; c < NUM_LABELS_; c++) {
                unsigned long long a = mul2(p0, Wp[c][0]);
                fma2(a, p1, Wp[c][1]);
                red[rr * NUM_LABELS_ + c][tid] = hsum2(a);   // conflict-free STS.32
            }
        }
        __syncthreads();

        // ---- reduce pass: 45 outputs (j = 5*pass+ol/9, c = ol%9).
        // 2 warps: warp0 lanes 0..22 -> ol 0..22; warp1 lanes 0..21 -> ol 23..44.
        // Row start granule 49*ol (odd stride) -> LDS.128 conflict-free.
        int ol = -1;
        if (wid == 0 && lane < 23) ol = lane;
        else if (wid == 1 && lane < 22) ol = 23 + lane;
        if (ol >= 0) {
            const float4* rp = (const float4*)red[ol];
            float4 t0 = rp[0], t1 = rp[1], t2 = rp[2], t3 = rp[3];
            float4 t4 = rp[4], t5 = rp[5], t6 = rp[6], t7 = rp[7];
            #pragma unroll
            for (int g = 8; g < 48; g += 8) {
                float4 u0 = rp[g], u1 = rp[g+1], u2 = rp[g+2], u3 = rp[g+3];
                float4 u4 = rp[g+4], u5 = rp[g+5], u6 = rp[g+6], u7 = rp[g+7];
                t0 = make_float4(t0.x + u0.x, t0.y + u0.y, t0.z + u0.z, t0.w + u0.w);
                t1 = make_float4(t1.x + u1.x, t1.y + u1.y, t1.z + u1.z, t1.w + u1.w);
                t2 = make_float4(t2.x + u2.x, t2.y + u2.y, t2.z + u2.z, t2.w + u2.w);
                t3 = make_float4(t3.x + u3.x, t3.y + u3.y, t3.z + u3.z, t3.w + u3.w);
                t4 = make_float4(t4.x + u4.x, t4.y + u4.y, t4.z + u4.z, t4.w + u4.w);
                t5 = make_float4(t5.x + u5.x, t5.y + u5.y, t5.z + u5.z, t5.w + u5.w);
                t6 = make_float4(t6.x + u6.x, t6.y + u6.y, t6.z + u6.z, t6.w + u6.w);
                t7 = make_float4(t7.x + u7.x, t7.y + u7.y, t7.z + u7.z, t7.w + u7.w);
            }
            t0 = make_float4(t0.x + t4.x, t0.y + t4.y, t0.z + t4.z, t0.w + t4.w);
            t1 = make_float4(t1.x + t5.x, t1.y + t5.y, t1.z + t5.z, t1.w + t5.w);
            t2 = make_float4(t2.x + t6.x, t2.y + t6.y, t2.z + t6.z, t2.w + t6.w);
            t3 = make_float4(t3.x + t7.x, t3.y + t7.y, t3.z + t7.z, t3.w + t7.w);
            t0 = make_float4(t0.x + t2.x, t0.y + t2.y, t0.z + t2.z, t0.w + t2.w);
            t1 = make_float4(t1.x + t3.x, t1.y + t3.y, t1.z + t3.z, t1.w + t3.w);
            const float tot = (t0.x + t1.x) + (t0.y + t1.y) + (t0.z + t1.z) + (t0.w + t1.w);

            const int jr = ol / NUM_LABELS_;
            const int c  = ol - NUM_LABELS_ * jr;
            const int j  = pass * 5 + jr;
            const int lm1 = (j < smax1) ? j : smax1;   // L-1 = min(j, S-1-start)
            out[(bn + j) * NUM_LABELS_ + c] = tot + g_len_logits[lm1 * NUM_LABELS_ + c];
        }
        __syncthreads();   // protect red before next pass overwrites it
    }
}

extern "C" void kernel_launch(void* const* d_in, const int* in_sizes, int n_in,
                              void* d_out, int out_size) {
    const float* we     = (const float*)d_in[0];   // word_embeddings [B,S,D]
    const int*   starts = (const int*)d_in[1];     // span_starts [B,N]
    const float* let    = (const float*)d_in[3];   // len_emb_table [MAX_LEN, LEN_EMB]
    const float* W      = (const float*)d_in[4];   // W [D+LEN_EMB, 9]
    const float* bvec   = (const float*)d_in[5];   // b [9]
    float* out = (float*)d_out;

    prep_kernel<<<(NUM_LABELS_ * D_ + 255) / 256, 256>>>(let, W, bvec);

    span_ner_kernel<<<B_ * S_, 192>>>(we, starts, out);
}